// round 4
// baseline (speedup 1.0000x reference)
#include <cuda_runtime.h>
#include <cstdint>

#define BB 8
#define C_IN 64
#define C_OUT 128
#define HH 256
#define WW 256
#define NK 8

#define TH 16
#define TW 64
#define COT 16          // c_out per block (8 warps x 2 each)
#define SROW 68         // padded smem row stride (floats)
#define CPR 2           // channels per round

__device__ float g_pooled[BB * C_IN];
__device__ float g_attn[BB * NK];
__device__ float g_mixed[BB * C_OUT * C_IN * 9];

typedef unsigned long long ull;

__device__ __forceinline__ ull pk(float lo, float hi) {
    ull r;
    asm("mov.b64 %0, {%1, %2};" : "=l"(r) : "f"(lo), "f"(hi));
    return r;
}
__device__ __forceinline__ void upk(float& lo, float& hi, ull v) {
    asm("mov.b64 {%0, %1}, %2;" : "=f"(lo), "=f"(hi) : "l"(v));
}
__device__ __forceinline__ ull ffma2(ull a, ull b, ull c) {
    ull d;
    asm("fma.rn.f32x2 %0, %1, %2, %3;" : "=l"(d) : "l"(a), "l"(b), "l"(c));
    return d;
}

// ---------------- Kernel 1: global average pool per (b, c_in) ----------------
__global__ void pool_kernel(const float* __restrict__ x) {
    int idx = blockIdx.x;  // b*C_IN + ci
    const float4* p = reinterpret_cast<const float4*>(x + (size_t)idx * (HH * WW));
    float s = 0.f;
    for (int i = threadIdx.x; i < (HH * WW) / 4; i += blockDim.x) {
        float4 v = p[i];
        s += v.x + v.y + v.z + v.w;
    }
    __shared__ float red[256];
    red[threadIdx.x] = s;
    __syncthreads();
    for (int off = 128; off > 0; off >>= 1) {
        if (threadIdx.x < off) red[threadIdx.x] += red[threadIdx.x + off];
        __syncthreads();
    }
    if (threadIdx.x == 0) g_pooled[idx] = red[0] * (1.0f / (HH * WW));
}

// ---------------- Kernel 2: logits + softmax -> attention weights ----------------
__global__ void attn_kernel(const float* __restrict__ attn_w,
                            const float* __restrict__ attn_b) {
    __shared__ float lg[BB * NK];
    int t = threadIdx.x;
    if (t < BB * NK) {
        int b = t / NK, n = t % NK;
        float s = attn_b[n];
        #pragma unroll 8
        for (int c = 0; c < C_IN; c++) s += g_pooled[b * C_IN + c] * attn_w[n * C_IN + c];
        lg[t] = s;
    }
    __syncthreads();
    if (t < BB) {
        float m = -1e30f;
        for (int n = 0; n < NK; n++) m = fmaxf(m, lg[t * NK + n]);
        float e[NK];
        float sum = 0.f;
        for (int n = 0; n < NK; n++) { e[n] = expf(lg[t * NK + n] - m); sum += e[n]; }
        float inv = 1.0f / sum;
        for (int n = 0; n < NK; n++) g_attn[t * NK + n] = e[n] * inv;
    }
}

// ---------------- Kernel 3: mix kernel bank by attention ----------------
__global__ void mix_kernel(const float* __restrict__ bank) {
    const int R = C_OUT * C_IN * 9;
    int i = blockIdx.x * blockDim.x + threadIdx.x;
    if (i >= BB * R) return;
    int b = i / R, r = i - b * R;
    float s = 0.f;
    #pragma unroll
    for (int n = 0; n < NK; n++) s += g_attn[b * NK + n] * bank[(size_t)n * R + r];
    g_mixed[i] = s;
}

// ---------------- Kernel 4: conv, f32x2 FMA, reg-staged double buffer ----------
// Block: 256 threads = 8 warps; tile 64x16, 16 c_out (2 per warp).
// Lane owns adjacent output cols (2l, 2l+1) packed in one f32x2.
// Smem row layout: [0]=col-1 halo, [1..64]=cols 0..63, [65]=col+64 halo,
// so p0=(c2l-1,c2l) and p2=(c2l+1,c2l+2) are single aligned LDS.64 each.
// Per round: 2 channels. Next round's gmem data is LDG'd into registers
// during compute (loop-invariant load plan), STS'd at round top.
__global__ void __launch_bounds__(256, 2) conv_kernel(const float* __restrict__ x,
                                                      float* __restrict__ out) {
    __shared__ float sx[CPR][TH + 2][SROW];
    __shared__ float swt[CPR][COT][9];

    const int tid = threadIdx.x;
    const int lane = tid & 31;
    const int wrp = tid >> 5;
    const int gx0 = blockIdx.x * TW;
    const int gy0 = blockIdx.y * TH;
    const int bz = blockIdx.z;            // b * (C_OUT/COT) + cog
    const int b = bz >> 3;                // C_OUT/COT = 8
    const int cobase = (bz & 7) * COT;

    const float* xb = x + (size_t)b * C_IN * (HH * WW);

    // ---- loop-invariant load plan ----
    // interior: 2ch x 18rows x 16 float4 = 576 slots
    int g_off[3]; bool g_val[3]; float* s_dst[3]; int g_ch[3];
    #pragma unroll
    for (int s = 0; s < 3; s++) {
        int i = tid + s * 256;
        g_val[s] = false; g_off[s] = 0; g_ch[s] = 0; s_dst[s] = &sx[0][0][0];
        if (i < 576) {
            int ch = i / 288, k = i - ch * 288;
            int rr = k >> 4, c4 = k & 15;
            int y = gy0 + rr - 1;
            g_ch[s] = ch;
            g_val[s] = (y >= 0) && (y < HH);
            g_off[s] = (g_val[s] ? y : 0) * WW + gx0 + c4 * 4;
            s_dst[s] = &sx[ch][rr][1 + c4 * 4];
        }
    }
    // halo cols: 2ch x 18rows x 2 = 72 slots
    bool h_act = tid < 72, h_val = false;
    int h_off = 0, h_ch = 0; float* h_dst = &sx[0][0][0];
    if (h_act) {
        int ch = tid / 36, k = tid - ch * 36;
        int r = k >> 1, side = k & 1;
        int y = gy0 + r - 1;
        int xc = side ? gx0 + 64 : gx0 - 1;
        h_ch = ch;
        h_val = (y >= 0) && (y < HH) && (xc >= 0) && (xc < WW);
        h_off = (h_val ? y * WW + xc : 0);
        h_dst = &sx[ch][r][side ? 65 : 0];
    }
    // weights: 2ch x 16cout x 9 = 288 slots; thread t does t and (t<32) t+256
    float* wflat = &swt[0][0][0];
    const float* w_src0;
    const float* w_src1 = nullptr;
    {
        int idx = tid;
        int ci2 = idx / 144, k = idx - ci2 * 144, col = k / 9, t = k - col * 9;
        w_src0 = g_mixed + (((size_t)b * C_OUT + cobase + col) * C_IN + ci2) * 9 + t;
        if (tid < 32) {
            idx = tid + 256;
            ci2 = idx / 144; k = idx - ci2 * 144; col = k / 9; t = k - col * 9;
            w_src1 = g_mixed + (((size_t)b * C_OUT + cobase + col) * C_IN + ci2) * 9 + t;
        }
    }

    ull accA[TH], accB[TH];
    #pragma unroll
    for (int i = 0; i < TH; i++) { accA[i] = 0ULL; accB[i] = 0ULL; }

    float4 rI[3]; float rH = 0.f, rw0 = 0.f, rw1 = 0.f;

    // preload round 0 (ci = 0)
    #pragma unroll
    for (int s = 0; s < 3; s++) {
        rI[s] = make_float4(0.f, 0.f, 0.f, 0.f);
        if (g_val[s])
            rI[s] = *reinterpret_cast<const float4*>(xb + (size_t)g_ch[s] * (HH * WW) + g_off[s]);
    }
    if (h_val) rH = xb[(size_t)h_ch * (HH * WW) + h_off];
    rw0 = *w_src0;
    if (tid < 32) rw1 = *w_src1;

    const int ROUNDS = C_IN / CPR;   // 32
    for (int rd = 0; rd < ROUNDS; rd++) {
        __syncthreads();   // previous compute done; safe to overwrite smem
        // stage registers -> smem
        #pragma unroll
        for (int s = 0; s < 3; s++) {
            if (tid + s * 256 < 576) {
                s_dst[s][0] = rI[s].x; s_dst[s][1] = rI[s].y;
                s_dst[s][2] = rI[s].z; s_dst[s][3] = rI[s].w;
            }
        }
        if (h_act) *h_dst = rH;
        wflat[tid] = rw0;
        if (tid < 32) wflat[256 + tid] = rw1;
        __syncthreads();

        // prefetch next round into registers (hidden behind compute)
        if (rd + 1 < ROUNDS) {
            int ci = (rd + 1) * CPR;
            #pragma unroll
            for (int s = 0; s < 3; s++) {
                if (tid + s * 256 < 576) {
                    float4 v = make_float4(0.f, 0.f, 0.f, 0.f);
                    if (g_val[s])
                        v = *reinterpret_cast<const float4*>(
                            xb + (size_t)(ci + g_ch[s]) * (HH * WW) + g_off[s]);
                    rI[s] = v;
                }
            }
            if (h_val) rH = xb[(size_t)(ci + h_ch) * (HH * WW) + h_off];
            rw0 = w_src0[ci * 9];
            if (tid < 32) rw1 = w_src1[ci * 9];
        }

        // compute the two staged channels
        #pragma unroll
        for (int ci2 = 0; ci2 < CPR; ci2++) {
            ull wA[9], wB[9];
            #pragma unroll
            for (int t = 0; t < 9; t++) {
                float a = swt[ci2][wrp][t];
                float c2 = swt[ci2][wrp + 8][t];
                wA[t] = pk(a, a);
                wB[t] = pk(c2, c2);
            }
            #pragma unroll
            for (int r = 0; r < TH + 2; r++) {
                const float* row = &sx[ci2][r][0];
                float2 q0 = *reinterpret_cast<const float2*>(row + 2 * lane);      // (c2l-1, c2l)
                float2 q2 = *reinterpret_cast<const float2*>(row + 2 * lane + 2);  // (c2l+1, c2l+2)
                ull p0 = pk(q0.x, q0.y);
                ull p1 = pk(q0.y, q2.x);
                ull p2 = pk(q2.x, q2.y);
                if (r < TH) {
                    accA[r] = ffma2(p0, wA[0], ffma2(p1, wA[1], ffma2(p2, wA[2], accA[r])));
                    accB[r] = ffma2(p0, wB[0], ffma2(p1, wB[1], ffma2(p2, wB[2], accB[r])));
                }
                if (r >= 1 && r - 1 < TH) {
                    accA[r-1] = ffma2(p0, wA[3], ffma2(p1, wA[4], ffma2(p2, wA[5], accA[r-1])));
                    accB[r-1] = ffma2(p0, wB[3], ffma2(p1, wB[4], ffma2(p2, wB[5], accB[r-1])));
                }
                if (r >= 2) {
                    accA[r-2] = ffma2(p0, wA[6], ffma2(p1, wA[7], ffma2(p2, wA[8], accA[r-2])));
                    accB[r-2] = ffma2(p0, wB[6], ffma2(p1, wB[7], ffma2(p2, wB[8], accB[r-2])));
                }
            }
        }
    }

    int co0 = cobase + wrp;
    int co1 = cobase + 8 + wrp;
    float* opA = out + (((size_t)b * C_OUT + co0) * HH + gy0) * WW + gx0 + 2 * lane;
    float* opB = out + (((size_t)b * C_OUT + co1) * HH + gy0) * WW + gx0 + 2 * lane;
    #pragma unroll
    for (int o = 0; o < TH; o++) {
        float lo, hi;
        upk(lo, hi, accA[o]);
        *reinterpret_cast<float2*>(&opA[o * WW]) = make_float2(lo, hi);
        upk(lo, hi, accB[o]);
        *reinterpret_cast<float2*>(&opB[o * WW]) = make_float2(lo, hi);
    }
}

extern "C" void kernel_launch(void* const* d_in, const int* in_sizes, int n_in,
                              void* d_out, int out_size) {
    const float* x    = (const float*)d_in[0];
    const float* bank = (const float*)d_in[1];
    const float* aw   = (const float*)d_in[2];
    const float* ab   = (const float*)d_in[3];
    float* out = (float*)d_out;

    pool_kernel<<<BB * C_IN, 256>>>(x);
    attn_kernel<<<1, 64>>>(aw, ab);
    mix_kernel<<<(BB * C_OUT * C_IN * 9 + 255) / 256, 256>>>(bank);

    dim3 g(WW / TW, HH / TH, BB * (C_OUT / COT));
    conv_kernel<<<g, 256>>>(x, out);
}

// round 5
// speedup vs baseline: 1.6197x; 1.6197x over previous
#include <cuda_runtime.h>
#include <cstdint>

#define BB 8
#define C_IN 64
#define C_OUT 128
#define HH 256
#define WW 256
#define NK 8

#define TH 16
#define TW 64
#define COT 16          // c_out per block (8 warps x 2 each)
#define SROW 68         // padded smem row stride (floats)
#define CPR 2           // channels per round

__device__ float g_pooled[BB * C_IN];
__device__ float g_attn[BB * NK];
__device__ float g_mixed[BB * C_OUT * C_IN * 9];

typedef unsigned long long ull;

__device__ __forceinline__ ull pk(float lo, float hi) {
    ull r;
    asm("mov.b64 %0, {%1, %2};" : "=l"(r) : "f"(lo), "f"(hi));
    return r;
}
__device__ __forceinline__ void upk(float& lo, float& hi, ull v) {
    asm("mov.b64 {%0, %1}, %2;" : "=f"(lo), "=f"(hi) : "l"(v));
}
__device__ __forceinline__ ull ffma2(ull a, ull b, ull c) {
    ull d;
    asm("fma.rn.f32x2 %0, %1, %2, %3;" : "=l"(d) : "l"(a), "l"(b), "l"(c));
    return d;
}

// ---------------- Kernel 1: global average pool per (b, c_in) ----------------
__global__ void pool_kernel(const float* __restrict__ x) {
    int idx = blockIdx.x;  // b*C_IN + ci
    const float4* p = reinterpret_cast<const float4*>(x + (size_t)idx * (HH * WW));
    float s = 0.f;
    for (int i = threadIdx.x; i < (HH * WW) / 4; i += blockDim.x) {
        float4 v = p[i];
        s += v.x + v.y + v.z + v.w;
    }
    __shared__ float red[256];
    red[threadIdx.x] = s;
    __syncthreads();
    for (int off = 128; off > 0; off >>= 1) {
        if (threadIdx.x < off) red[threadIdx.x] += red[threadIdx.x + off];
        __syncthreads();
    }
    if (threadIdx.x == 0) g_pooled[idx] = red[0] * (1.0f / (HH * WW));
}

// ---------------- Kernel 2: logits + softmax -> attention weights ----------------
__global__ void attn_kernel(const float* __restrict__ attn_w,
                            const float* __restrict__ attn_b) {
    __shared__ float lg[BB * NK];
    int t = threadIdx.x;
    if (t < BB * NK) {
        int b = t / NK, n = t % NK;
        float s = attn_b[n];
        #pragma unroll 8
        for (int c = 0; c < C_IN; c++) s += g_pooled[b * C_IN + c] * attn_w[n * C_IN + c];
        lg[t] = s;
    }
    __syncthreads();
    if (t < BB) {
        float m = -1e30f;
        for (int n = 0; n < NK; n++) m = fmaxf(m, lg[t * NK + n]);
        float e[NK];
        float sum = 0.f;
        for (int n = 0; n < NK; n++) { e[n] = expf(lg[t * NK + n] - m); sum += e[n]; }
        float inv = 1.0f / sum;
        for (int n = 0; n < NK; n++) g_attn[t * NK + n] = e[n] * inv;
    }
}

// ---------------- Kernel 3: mix kernel bank by attention ----------------
__global__ void mix_kernel(const float* __restrict__ bank) {
    const int R = C_OUT * C_IN * 9;
    int i = blockIdx.x * blockDim.x + threadIdx.x;
    if (i >= BB * R) return;
    int b = i / R, r = i - b * R;
    float s = 0.f;
    #pragma unroll
    for (int n = 0; n < NK; n++) s += g_attn[b * NK + n] * bank[(size_t)n * R + r];
    g_mixed[i] = s;
}

// ---------------- Kernel 4: conv, f32x2 FMA, reg-staged double buffer ----------
// Block: 256 threads = 8 warps; tile 64x16, 16 c_out (2 per warp).
// Lane owns adjacent output cols (2l, 2l+1) packed in one f32x2.
// Smem row layout: [0]=col-1 halo, [1..64]=cols 0..63, [65]=col+64 halo,
// so p0=(c2l-1,c2l) and p2=(c2l+1,c2l+2) are single aligned LDS.64 each.
// Per round: 2 channels. Next round's gmem data is LDG'd into registers
// during compute (loop-invariant load plan), STS'd at round top.
__global__ void __launch_bounds__(256, 2) conv_kernel(const float* __restrict__ x,
                                                      float* __restrict__ out) {
    __shared__ float sx[CPR][TH + 2][SROW];
    __shared__ float swt[CPR][COT][9];

    const int tid = threadIdx.x;
    const int lane = tid & 31;
    const int wrp = tid >> 5;
    const int gx0 = blockIdx.x * TW;
    const int gy0 = blockIdx.y * TH;
    const int bz = blockIdx.z;            // b * (C_OUT/COT) + cog
    const int b = bz >> 3;                // C_OUT/COT = 8
    const int cobase = (bz & 7) * COT;

    const float* xb = x + (size_t)b * C_IN * (HH * WW);

    // ---- loop-invariant load plan ----
    // interior: 2ch x 18rows x 16 float4 = 576 slots
    int g_off[3]; bool g_val[3]; float* s_dst[3]; int g_ch[3];
    #pragma unroll
    for (int s = 0; s < 3; s++) {
        int i = tid + s * 256;
        g_val[s] = false; g_off[s] = 0; g_ch[s] = 0; s_dst[s] = &sx[0][0][0];
        if (i < 576) {
            int ch = i / 288, k = i - ch * 288;
            int rr = k >> 4, c4 = k & 15;
            int y = gy0 + rr - 1;
            g_ch[s] = ch;
            g_val[s] = (y >= 0) && (y < HH);
            g_off[s] = (g_val[s] ? y : 0) * WW + gx0 + c4 * 4;
            s_dst[s] = &sx[ch][rr][1 + c4 * 4];
        }
    }
    // halo cols: 2ch x 18rows x 2 = 72 slots
    bool h_act = tid < 72, h_val = false;
    int h_off = 0, h_ch = 0; float* h_dst = &sx[0][0][0];
    if (h_act) {
        int ch = tid / 36, k = tid - ch * 36;
        int r = k >> 1, side = k & 1;
        int y = gy0 + r - 1;
        int xc = side ? gx0 + 64 : gx0 - 1;
        h_ch = ch;
        h_val = (y >= 0) && (y < HH) && (xc >= 0) && (xc < WW);
        h_off = (h_val ? y * WW + xc : 0);
        h_dst = &sx[ch][r][side ? 65 : 0];
    }
    // weights: 2ch x 16cout x 9 = 288 slots; thread t does t and (t<32) t+256
    float* wflat = &swt[0][0][0];
    const float* w_src0;
    const float* w_src1 = nullptr;
    {
        int idx = tid;
        int ci2 = idx / 144, k = idx - ci2 * 144, col = k / 9, t = k - col * 9;
        w_src0 = g_mixed + (((size_t)b * C_OUT + cobase + col) * C_IN + ci2) * 9 + t;
        if (tid < 32) {
            idx = tid + 256;
            ci2 = idx / 144; k = idx - ci2 * 144; col = k / 9; t = k - col * 9;
            w_src1 = g_mixed + (((size_t)b * C_OUT + cobase + col) * C_IN + ci2) * 9 + t;
        }
    }

    ull accA[TH], accB[TH];
    #pragma unroll
    for (int i = 0; i < TH; i++) { accA[i] = 0ULL; accB[i] = 0ULL; }

    float4 rI[3]; float rH = 0.f, rw0 = 0.f, rw1 = 0.f;

    // preload round 0 (ci = 0)
    #pragma unroll
    for (int s = 0; s < 3; s++) {
        rI[s] = make_float4(0.f, 0.f, 0.f, 0.f);
        if (g_val[s])
            rI[s] = *reinterpret_cast<const float4*>(xb + (size_t)g_ch[s] * (HH * WW) + g_off[s]);
    }
    if (h_val) rH = xb[(size_t)h_ch * (HH * WW) + h_off];
    rw0 = *w_src0;
    if (tid < 32) rw1 = *w_src1;

    const int ROUNDS = C_IN / CPR;   // 32
    for (int rd = 0; rd < ROUNDS; rd++) {
        __syncthreads();   // previous compute done; safe to overwrite smem
        // stage registers -> smem
        #pragma unroll
        for (int s = 0; s < 3; s++) {
            if (tid + s * 256 < 576) {
                s_dst[s][0] = rI[s].x; s_dst[s][1] = rI[s].y;
                s_dst[s][2] = rI[s].z; s_dst[s][3] = rI[s].w;
            }
        }
        if (h_act) *h_dst = rH;
        wflat[tid] = rw0;
        if (tid < 32) wflat[256 + tid] = rw1;
        __syncthreads();

        // prefetch next round into registers (hidden behind compute)
        if (rd + 1 < ROUNDS) {
            int ci = (rd + 1) * CPR;
            #pragma unroll
            for (int s = 0; s < 3; s++) {
                if (tid + s * 256 < 576) {
                    float4 v = make_float4(0.f, 0.f, 0.f, 0.f);
                    if (g_val[s])
                        v = *reinterpret_cast<const float4*>(
                            xb + (size_t)(ci + g_ch[s]) * (HH * WW) + g_off[s]);
                    rI[s] = v;
                }
            }
            if (h_val) rH = xb[(size_t)(ci + h_ch) * (HH * WW) + h_off];
            rw0 = w_src0[ci * 9];
            if (tid < 32) rw1 = w_src1[ci * 9];
        }

        // compute the two staged channels
        #pragma unroll
        for (int ci2 = 0; ci2 < CPR; ci2++) {
            ull wA[9], wB[9];
            #pragma unroll
            for (int t = 0; t < 9; t++) {
                float a = swt[ci2][wrp][t];
                float c2 = swt[ci2][wrp + 8][t];
                wA[t] = pk(a, a);
                wB[t] = pk(c2, c2);
            }
            #pragma unroll
            for (int r = 0; r < TH + 2; r++) {
                const float* row = &sx[ci2][r][0];
                float2 q0 = *reinterpret_cast<const float2*>(row + 2 * lane);      // (c2l-1, c2l)
                float2 q2 = *reinterpret_cast<const float2*>(row + 2 * lane + 2);  // (c2l+1, c2l+2)
                ull p0 = pk(q0.x, q0.y);
                ull p1 = pk(q0.y, q2.x);
                ull p2 = pk(q2.x, q2.y);
                if (r < TH) {
                    accA[r] = ffma2(p0, wA[0], ffma2(p1, wA[1], ffma2(p2, wA[2], accA[r])));
                    accB[r] = ffma2(p0, wB[0], ffma2(p1, wB[1], ffma2(p2, wB[2], accB[r])));
                }
                if (r >= 1 && r - 1 < TH) {
                    accA[r-1] = ffma2(p0, wA[3], ffma2(p1, wA[4], ffma2(p2, wA[5], accA[r-1])));
                    accB[r-1] = ffma2(p0, wB[3], ffma2(p1, wB[4], ffma2(p2, wB[5], accB[r-1])));
                }
                if (r >= 2) {
                    accA[r-2] = ffma2(p0, wA[6], ffma2(p1, wA[7], ffma2(p2, wA[8], accA[r-2])));
                    accB[r-2] = ffma2(p0, wB[6], ffma2(p1, wB[7], ffma2(p2, wB[8], accB[r-2])));
                }
            }
        }
    }

    int co0 = cobase + wrp;
    int co1 = cobase + 8 + wrp;
    float* opA = out + (((size_t)b * C_OUT + co0) * HH + gy0) * WW + gx0 + 2 * lane;
    float* opB = out + (((size_t)b * C_OUT + co1) * HH + gy0) * WW + gx0 + 2 * lane;
    #pragma unroll
    for (int o = 0; o < TH; o++) {
        float lo, hi;
        upk(lo, hi, accA[o]);
        *reinterpret_cast<float2*>(&opA[o * WW]) = make_float2(lo, hi);
        upk(lo, hi, accB[o]);
        *reinterpret_cast<float2*>(&opB[o * WW]) = make_float2(lo, hi);
    }
}

extern "C" void kernel_launch(void* const* d_in, const int* in_sizes, int n_in,
                              void* d_out, int out_size) {
    const float* x    = (const float*)d_in[0];
    const float* bank = (const float*)d_in[1];
    const float* aw   = (const float*)d_in[2];
    const float* ab   = (const float*)d_in[3];
    float* out = (float*)d_out;

    pool_kernel<<<BB * C_IN, 256>>>(x);
    attn_kernel<<<1, 64>>>(aw, ab);
    mix_kernel<<<(BB * C_OUT * C_IN * 9 + 255) / 256, 256>>>(bank);

    dim3 g(WW / TW, HH / TH, BB * (C_OUT / COT));
    conv_kernel<<<g, 256>>>(x, out);
}